// round 1
// baseline (speedup 1.0000x reference)
#include <cuda_runtime.h>
#include <cuda_bf16.h>

// GraphConvolution — reference reduces algebraically:
//   s = W - W^T is exactly skew in fp32, so m_left.T == m_right bitwise and
//   ortho_weight = solve(m_right, m_right)^T = I (to ~3e-5, the reference's own
//   LU roundoff). Hence support = x and the kernel is a COO SpMM:
//     out[r] = sum_{e: row[e]=r} val[e]*x[col[e],:] + x_0[r] + bias
//
// Kernel 1: out = x_0 + bias          (init; d_out is poisoned 0xAA)
// Kernel 2: vectorized red.global.add.v4.f32 scatter, 16 threads per edge
//           (each thread owns one float4 chunk of the 64-float row).

#define FEAT4 16   // D/4 = 64/4 float4 chunks per row

__global__ void init_out_kernel(const float4* __restrict__ x0,
                                const float4* __restrict__ bias4,
                                float4* __restrict__ out4,
                                int n4) {
    int i = blockIdx.x * blockDim.x + threadIdx.x;
    if (i >= n4) return;
    float4 b = bias4[i & (FEAT4 - 1)];
    float4 v = x0[i];
    out4[i] = make_float4(v.x + b.x, v.y + b.y, v.z + b.z, v.w + b.w);
}

__global__ void edge_scatter_kernel(const float4* __restrict__ x4,
                                    const float* __restrict__ edge_val,
                                    const int* __restrict__ edge_row,
                                    const int* __restrict__ edge_col,
                                    float4* __restrict__ out4,
                                    int n_edges) {
    int t = blockIdx.x * blockDim.x + threadIdx.x;
    int e = t >> 4;          // edge index (16 threads per edge)
    if (e >= n_edges) return;
    int c = t & (FEAT4 - 1); // float4 chunk within the 64-float row

    // 16 lanes share the same edge metadata -> single sector, broadcast
    int   col = __ldg(edge_col + e);
    int   row = __ldg(edge_row + e);
    float v   = __ldg(edge_val + e);

    // Contiguous 256B gather across the 16-lane group; x fits in L2 (16MB)
    float4 xv = __ldg(x4 + (size_t)col * FEAT4 + c);

    float4* dst = out4 + (size_t)row * FEAT4 + c;
    // Vectorized no-return reduction: 1 RED.128 instead of 4 scalar atomics
    asm volatile("red.global.add.v4.f32 [%0], {%1, %2, %3, %4};"
                 :: "l"(dst),
                    "f"(xv.x * v), "f"(xv.y * v), "f"(xv.z * v), "f"(xv.w * v)
                 : "memory");
}

extern "C" void kernel_launch(void* const* d_in, const int* in_sizes, int n_in,
                              void* d_out, int out_size) {
    // metadata order: x, x_0, edge_val, weight, bias, edge_row, edge_col
    const float4* x4    = (const float4*)d_in[0];
    const float4* x0_4  = (const float4*)d_in[1];
    const float*  ev    = (const float*)d_in[2];
    // d_in[3] = weight: unused (Cayley transform is algebraically identity here)
    const float4* bias4 = (const float4*)d_in[4];
    const int*    erow  = (const int*)d_in[5];
    const int*    ecol  = (const int*)d_in[6];
    float4*       out4  = (float4*)d_out;

    int n_edges = in_sizes[2];       // E
    int n4      = in_sizes[1] / 4;   // N*D/4 float4s

    const int TB = 256;

    init_out_kernel<<<(n4 + TB - 1) / TB, TB>>>(x0_4, bias4, out4, n4);

    long long total_threads = (long long)n_edges * FEAT4;
    int blocks = (int)((total_threads + TB - 1) / TB);
    edge_scatter_kernel<<<blocks, TB>>>(x4, ev, erow, ecol, out4, n_edges);
}